// round 13
// baseline (speedup 1.0000x reference)
#include <cuda_runtime.h>

#define SDIM   128
#define DIM    480           // 128 + 64*3 + 32*5
#define RPB    4             // rows per block
#define NTHR   128
#define EPS    1e-5f

__device__ __forceinline__ float ldcs_f(const float* p) {
    float v;
    asm volatile("ld.global.cs.f32 %0, [%1];" : "=f"(v) : "l"(p));
    return v;
}
__device__ __forceinline__ float4 ldcs_f4(const float4* p) {
    float4 v;
    asm volatile("ld.global.cs.v4.f32 {%0,%1,%2,%3}, [%4];"
                 : "=f"(v.x), "=f"(v.y), "=f"(v.z), "=f"(v.w) : "l"(p));
    return v;
}
__device__ __forceinline__ void stcs_f(float* p, float v) {
    asm volatile("st.global.cs.f32 [%0], %1;" :: "l"(p), "f"(v));
}
__device__ __forceinline__ void stcs_f4(float4* p, float4 v) {
    asm volatile("st.global.cs.v4.f32 [%0], {%1,%2,%3,%4};"
                 :: "l"(p), "f"(v.x), "f"(v.y), "f"(v.z), "f"(v.w));
}

__global__ __launch_bounds__(NTHR) void eln_kernel(
    const float* __restrict__ x,
    const float* __restrict__ weight,
    const float* __restrict__ bias,
    float* __restrict__ out)
{
    const int tid  = threadIdx.x;
    const int lane = tid & 31;
    const int wrp  = tid >> 5;
    const long long row0 = (long long)blockIdx.x * RPB;

    // ================= front-batch ALL global loads =================
    const float4 w4 = __ldg((const float4*)weight + lane);
    const float4 b4 = __ldg((const float4*)bias   + lane);

    // scalar region: warp w owns row (row0+w), 32 x LDG.128
    const float4 sv = ldcs_f4((const float4*)(x + (row0 + wrp) * DIM) + lane);

    // seg3: 256 segments (4 rows x 64), 2 per thread, strided LDG.32
    // iter j: seg id = j*128 + tid -> row = id/64, col = id%64
    const int id3a = tid;            // j=0: rows 0..1
    const int id3b = 128 + tid;      // j=1: rows 2..3
    const float* p3a = x + (row0 + (id3a >> 6)) * DIM + SDIM + 3 * (id3a & 63);
    const float* p3b = x + (row0 + (id3b >> 6)) * DIM + SDIM + 3 * (id3b & 63);
    float a0 = ldcs_f(p3a + 0), a1 = ldcs_f(p3a + 1), a2 = ldcs_f(p3a + 2);
    float c0 = ldcs_f(p3b + 0), c1 = ldcs_f(p3b + 1), c2 = ldcs_f(p3b + 2);

    // seg5: 128 segments (4 rows x 32), 1 per thread
    const float* p5 = x + (row0 + (tid >> 5)) * DIM + SDIM + 192 + 5 * (tid & 31);
    float e0 = ldcs_f(p5 + 0), e1 = ldcs_f(p5 + 1), e2 = ldcs_f(p5 + 2);
    float e3 = ldcs_f(p5 + 3), e4 = ldcs_f(p5 + 4);

    // ================= scalar layernorm (warp-local) =================
    float sum = sv.x + sv.y + sv.z + sv.w;
    float sq  = sv.x * sv.x + sv.y * sv.y + sv.z * sv.z + sv.w * sv.w;
    #pragma unroll
    for (int o = 16; o; o >>= 1) {
        sum += __shfl_xor_sync(0xFFFFFFFFu, sum, o);
        sq  += __shfl_xor_sync(0xFFFFFFFFu, sq,  o);
    }
    const float m  = sum * (1.0f / 128.0f);
    const float rs = rsqrtf(sq * (1.0f / 128.0f) - m * m + EPS);
    float4 so;
    so.x = (sv.x - m) * rs * w4.x + b4.x;
    so.y = (sv.y - m) * rs * w4.y + b4.y;
    so.z = (sv.z - m) * rs * w4.z + b4.z;
    so.w = (sv.w - m) * rs * w4.w + b4.w;
    stcs_f4((float4*)(out + (row0 + wrp) * DIM) + lane, so);

    // ================= seg3 #1 =================
    {
        float sm = (a0 + a1 + a2) * (1.0f / 3.0f);
        float d0 = a0 - sm, d1 = a1 - sm, d2 = a2 - sm;
        float rr = rsqrtf((d0 * d0 + d1 * d1 + d2 * d2) * (1.0f / 3.0f) + EPS);
        float* q = out + (row0 + (id3a >> 6)) * DIM + SDIM + 3 * (id3a & 63);
        stcs_f(q + 0, d0 * rr);
        stcs_f(q + 1, d1 * rr);
        stcs_f(q + 2, d2 * rr);
    }
    // ================= seg3 #2 =================
    {
        float sm = (c0 + c1 + c2) * (1.0f / 3.0f);
        float d0 = c0 - sm, d1 = c1 - sm, d2 = c2 - sm;
        float rr = rsqrtf((d0 * d0 + d1 * d1 + d2 * d2) * (1.0f / 3.0f) + EPS);
        float* q = out + (row0 + (id3b >> 6)) * DIM + SDIM + 3 * (id3b & 63);
        stcs_f(q + 0, d0 * rr);
        stcs_f(q + 1, d1 * rr);
        stcs_f(q + 2, d2 * rr);
    }
    // ================= seg5 =================
    {
        float sm = (e0 + e1 + e2 + e3 + e4) * 0.2f;
        float d0 = e0 - sm, d1 = e1 - sm, d2 = e2 - sm, d3 = e3 - sm, d4 = e4 - sm;
        float rr = rsqrtf((d0 * d0 + d1 * d1 + d2 * d2 + d3 * d3 + d4 * d4) * 0.2f + EPS);
        float* q = out + (row0 + (tid >> 5)) * DIM + SDIM + 192 + 5 * (tid & 31);
        stcs_f(q + 0, d0 * rr);
        stcs_f(q + 1, d1 * rr);
        stcs_f(q + 2, d2 * rr);
        stcs_f(q + 3, d3 * rr);
        stcs_f(q + 4, d4 * rr);
    }
}

extern "C" void kernel_launch(void* const* d_in, const int* in_sizes, int n_in,
                              void* d_out, int out_size)
{
    const float* x      = (const float*)d_in[0];
    const float* weight = (const float*)d_in[1];
    const float* bias   = (const float*)d_in[2];
    float* out = (float*)d_out;

    const int n_rows = in_sizes[0] / DIM;   // 262144
    eln_kernel<<<n_rows / RPB, NTHR>>>(x, weight, bias, out);
}